// round 14
// baseline (speedup 1.0000x reference)
#include <cuda_runtime.h>
#include <cuda_fp16.h>
#include <math.h>
#include <stdint.h>

#define BB 512
#define TT 128
#define FF 1024
#define HH 1024
#define NOUT 256
#define FOURH 4096
#define BT 65536

typedef __half h16;

// ---------------------------------------------------------------------------
// Device-global scratch (sorted-batch order unless noted)
// ---------------------------------------------------------------------------
__device__ float g_xw[(size_t)BT * FOURH];     // X @ Wx + b, gate-interleaved cols
__device__ float g_c[BB * HH];
__device__ float g_h[BB * HH];
__device__ float g_bias[FOURH];                // permuted bias
__device__ h16   g_x16[(size_t)BT * FF];       // X as fp16 (ORIGINAL batch order; active rows only)
__device__ h16   g_f16[(size_t)BT * HH];       // masked h outputs (zero-init; inactive rows never written)
__device__ h16   g_h16[2][BB * HH];            // double-buffered h state, fp16
__device__ h16   g_wx_hi[(size_t)FOURH * FF];  // Wx^T [4H,F] K-major, interleaved rows
__device__ h16   g_wh_hi[(size_t)FOURH * HH];  // Wh^T (single fp16 term now)
__device__ h16   g_wo_hi[NOUT * HH];
__device__ int   g_perm[BB];                   // sorted idx -> original idx
__device__ int   g_seqp[BB];                   // seq_len in sorted order (descending)
__device__ int   g_nact[TT];                   // #batches with seq_len > t
__device__ int   g_rowoff[BB];                 // prefix sum of seqp
__device__ int   g_total[1];                   // total active rows
__device__ int   g_rows[BT + 128];             // packed i -> sorted flat row (bp*TT+t)
__device__ int   g_rowsrc[BT + 128];           // packed i -> original flat row (perm[bp]*TT+t)

// ---------------------------------------------------------------------------
// Baseline-PTX helpers (legal on plain sm_103 target)
// ---------------------------------------------------------------------------
__device__ __forceinline__ uint32_t smem_u32(const void* p) {
    uint32_t a;
    asm("{ .reg .u64 t; cvta.to.shared.u64 t, %1; cvt.u32.u64 %0, t; }"
        : "=r"(a) : "l"(p));
    return a;
}
__device__ __forceinline__ void cp16(uint32_t dst, const void* src) {
    asm volatile("cp.async.cg.shared.global [%0], [%1], 16;"
                 :: "r"(dst), "l"(src) : "memory");
}
__device__ __forceinline__ void ldsm4(uint32_t* r, uint32_t addr) {
    asm volatile("ldmatrix.sync.aligned.m8n8.x4.shared.b16 {%0,%1,%2,%3}, [%4];"
                 : "=r"(r[0]), "=r"(r[1]), "=r"(r[2]), "=r"(r[3]) : "r"(addr));
}
__device__ __forceinline__ void mma16816(float* d, const uint32_t* a, const uint32_t* b) {
    asm volatile(
        "mma.sync.aligned.m16n8k16.row.col.f32.f16.f16.f32 "
        "{%0,%1,%2,%3}, {%4,%5,%6,%7}, {%8,%9}, {%0,%1,%2,%3};"
        : "+f"(d[0]), "+f"(d[1]), "+f"(d[2]), "+f"(d[3])
        : "r"(a[0]), "r"(a[1]), "r"(a[2]), "r"(a[3]), "r"(b[0]), "r"(b[1]));
}

// ---------------------------------------------------------------------------
// GEMM tile machinery. BM=MT*32 rows, BN=NT*32 cols, BK=32, 256 threads
// (8 warps: 2 row-groups x 4 col-groups). NB = B terms. NST = stages.
// PACKED: A rows gathered through an index array.
// ---------------------------------------------------------------------------
#define ROWB 80

template <int MT, int NT, int NB, bool PACKED>
__device__ __forceinline__ void load_stage(
    uint32_t stg, const h16* __restrict__ A, const int* __restrict__ aidx,
    const h16* __restrict__ Bh, const h16* __restrict__ Bl,
    int n0, int k0, int K, int tid)
{
    constexpr int BM = MT * 32;
    constexpr int BN = NT * 32;
    constexpr uint32_t OFFB = (uint32_t)BM * ROWB;
    constexpr uint32_t BTERM = (uint32_t)BN * ROWB;
#pragma unroll
    for (int i = 0; i < BM * 4 / 256; i++) {
        const int c = tid + i * 256;
        const int row = c >> 2;
        const int seg = c & 3;
        const h16* src = PACKED ? A + (size_t)aidx[row] * K + k0 + seg * 8
                                : A + (size_t)row * K + k0 + seg * 8;
        cp16(stg + (uint32_t)(row * ROWB + seg * 16), src);
    }
#pragma unroll
    for (int i = 0; i < BN * 4 / 256; i++) {
        const int c = tid + i * 256;
        const int row = c >> 2;
        const int seg = c & 3;
        const uint32_t soff = (uint32_t)(row * ROWB + seg * 16);
        const size_t gb = (size_t)(n0 + row) * K + k0 + seg * 8;
        cp16(stg + OFFB + soff, Bh + gb);
        if (NB == 2) cp16(stg + OFFB + BTERM + soff, Bl + gb);
    }
}

template <int MT, int NT, int NB, int NST, bool PACKED>
__device__ __forceinline__ void gemm_mainloop(
    uint32_t SM, const h16* __restrict__ A, const int* __restrict__ aidx,
    const h16* __restrict__ Bh, const h16* __restrict__ Bl,
    int n0, int K, int tid, float acc[MT][NT][4])
{
    constexpr int BM = MT * 32;
    constexpr int BN = NT * 32;
    constexpr uint32_t OFFB = (uint32_t)BM * ROWB;
    constexpr uint32_t BTERM = (uint32_t)BN * ROWB;
    constexpr uint32_t STG_B = OFFB + NB * BTERM;
    const int lane = tid & 31;
    const int wid  = tid >> 5;
    const int wm   = wid & 1;
    const int wn   = wid >> 1;
    const int NC = K >> 5;

#pragma unroll
    for (int s = 0; s < NST - 1; s++) {
        load_stage<MT, NT, NB, PACKED>(SM + s * STG_B, A, aidx, Bh, Bl, n0, s * 32, K, tid);
        asm volatile("cp.async.commit_group;" ::: "memory");
    }

    const int arow = wm * (MT * 16) + (lane & 15);
    const uint32_t akoff = (uint32_t)((lane >> 4) * 16);
    const int bsel = lane >> 3;
    const int bn = wn * (NT * 8) + ((bsel >> 1) << 3) + (lane & 7);
    const uint32_t bkoff = (uint32_t)((bsel & 1) * 16);

    for (int it = 0; it < NC; it++) {
        asm volatile("cp.async.wait_group %0;" :: "n"(NST - 2) : "memory");
        __syncthreads();

        const int nx = it + NST - 1;
        if (nx < NC)
            load_stage<MT, NT, NB, PACKED>(SM + (uint32_t)(nx % NST) * STG_B,
                                           A, aidx, Bh, Bl, n0, nx * 32, K, tid);
        asm volatile("cp.async.commit_group;" ::: "memory");

        const uint32_t stg = SM + (uint32_t)(it % NST) * STG_B;
#pragma unroll
        for (int ks = 0; ks < 2; ks++) {
            uint32_t ah[MT][4], bh[NT][2], bl[NT][2];
            const uint32_t ak = (uint32_t)(ks * 32) + akoff;
#pragma unroll
            for (int mt = 0; mt < MT; mt++)
                ldsm4(ah[mt], stg + (uint32_t)((arow + mt * 16) * ROWB) + ak);
            const uint32_t bk = (uint32_t)(ks * 32) + bkoff;
#pragma unroll
            for (int np = 0; np < NT / 2; np++) {
                const uint32_t bd = stg + OFFB + (uint32_t)((bn + np * 16) * ROWB) + bk;
                uint32_t tr[4];
                ldsm4(tr, bd);
                bh[2 * np][0] = tr[0]; bh[2 * np][1] = tr[1];
                bh[2 * np + 1][0] = tr[2]; bh[2 * np + 1][1] = tr[3];
                if (NB == 2) {
                    ldsm4(tr, bd + BTERM);
                    bl[2 * np][0] = tr[0]; bl[2 * np][1] = tr[1];
                    bl[2 * np + 1][0] = tr[2]; bl[2 * np + 1][1] = tr[3];
                }
            }
#pragma unroll
            for (int mt = 0; mt < MT; mt++)
#pragma unroll
                for (int nt = 0; nt < NT; nt++) {
                    mma16816(acc[mt][nt], ah[mt], bh[nt]);
                    if (NB == 2) mma16816(acc[mt][nt], ah[mt], bl[nt]);
                }
        }
    }
}

// Scatter epilogue: per-row destination via rows[], valid rows only (+bias).
template <int MT, int NT>
__device__ __forceinline__ void store_scatter(
    float acc[MT][NT][4], float* __restrict__ Cbase, const int* __restrict__ rows,
    const float* __restrict__ bias, int N, int n0, int tid, int nvalid)
{
    const int lane = tid & 31;
    const int wid  = tid >> 5;
    const int wm   = wid & 1;
    const int wn   = wid >> 1;
    const int colq = (lane & 3) * 2;
    const int rowq = lane >> 2;
    float bx[NT], by[NT];
#pragma unroll
    for (int nt = 0; nt < NT; nt++) {
        const int col = wn * (NT * 8) + nt * 8 + colq;
        float2 bv = *(const float2*)(bias + n0 + col);
        bx[nt] = bv.x; by[nt] = bv.y;
    }
#pragma unroll
    for (int mt = 0; mt < MT; mt++) {
        const int r0 = wm * (MT * 16) + mt * 16 + rowq;
#pragma unroll
        for (int half = 0; half < 2; half++) {
            const int rloc = r0 + half * 8;
            if (rloc < nvalid) {
                float* C = Cbase + (size_t)rows[rloc] * N;
#pragma unroll
                for (int nt = 0; nt < NT; nt++) {
                    const int col = wn * (NT * 8) + nt * 8 + colq;
                    *(float2*)(C + n0 + col) =
                        make_float2(acc[mt][nt][2 * half] + bx[nt],
                                    acc[mt][nt][2 * half + 1] + by[nt]);
                }
            }
        }
    }
}

// ---------------------------------------------------------------------------
// Packed XW GEMM: BM=128 (MT=4), NT=4, 4 stages, single weight term.
// ---------------------------------------------------------------------------
#define SMEM_X (4 * (128 * ROWB + 128 * ROWB))   // 81920
__global__ __launch_bounds__(256, 2)
void gemm_xw_packed()
{
    const int ts = blockIdx.y * 128;
    const int total = g_total[0];
    if (ts >= total) return;
    extern __shared__ char smem_raw[];
    const uint32_t SM = smem_u32(smem_raw);
    const int tid = threadIdx.x;
    const int n0 = blockIdx.x * 128;

    float acc[4][4][4];
#pragma unroll
    for (int a = 0; a < 4; a++)
#pragma unroll
        for (int b = 0; b < 4; b++)
#pragma unroll
            for (int cc = 0; cc < 4; cc++) acc[a][b][cc] = 0.0f;

    gemm_mainloop<4, 4, 1, 4, true>(SM, g_x16, g_rowsrc + ts, g_wx_hi, nullptr,
                                    n0, FF, tid, acc);
    store_scatter<4, 4>(acc, g_xw, g_rows + ts, g_bias, FOURH, n0, tid, total - ts);
}

// ---------------------------------------------------------------------------
// Packed head GEMM: BM=64 tiles (MT=2).
// ---------------------------------------------------------------------------
#define SMEM_H (4 * (64 * ROWB + 128 * ROWB))    // 61440
__global__ __launch_bounds__(256, 2)
void gemm_head_packed(const float* __restrict__ bout, float* __restrict__ out)
{
    const int ts = blockIdx.y * 64;
    const int total = g_total[0];
    if (ts >= total) return;
    extern __shared__ char smem_raw[];
    const uint32_t SM = smem_u32(smem_raw);
    const int tid = threadIdx.x;
    const int n0 = blockIdx.x * 128;

    float acc[2][4][4];
#pragma unroll
    for (int a = 0; a < 2; a++)
#pragma unroll
        for (int b = 0; b < 4; b++)
#pragma unroll
            for (int cc = 0; cc < 4; cc++) acc[a][b][cc] = 0.0f;

    gemm_mainloop<2, 4, 1, 4, true>(SM, g_f16, g_rows + ts, g_wo_hi, nullptr,
                                    n0, HH, tid, acc);
    store_scatter<2, 4>(acc, out, g_rowsrc + ts, bout, NOUT, n0, tid, total - ts);
}

// Bias fill for inactive head rows (logits = bias there).
__global__ void head_bias_fill(const float* __restrict__ bout, float* __restrict__ out)
{
    const int bp = blockIdx.x;
    const int s = g_seqp[bp];
    const int nrows = TT - s;
    if (nrows <= 0) return;
    const size_t base = ((size_t)g_perm[bp] * TT + s) * NOUT;
    for (int i = threadIdx.x; i < nrows * 64; i += 256) {
        const int r = i >> 6;
        const int c = (i & 63) * 4;
        *(float4*)(out + base + (size_t)r * NOUT + c) = *(const float4*)(bout + c);
    }
}

// ---------------------------------------------------------------------------
// Fused recurrent step: BM=64, BN=64 (NT=2), SINGLE-term Wh, 3 stages.
// Per-step launch; prefix-active skip; double-buffered h.
// ---------------------------------------------------------------------------
#define SMEM_REC (3 * (64 * ROWB + 64 * ROWB))   // 30720
__device__ __forceinline__ float sigf(float x) { return 1.0f / (1.0f + expf(-x)); }
__device__ __forceinline__ void splitw(float v, h16& hi, h16& lo) {
    hi = __float2half(v);
    lo = __float2half(v - __half2float(hi));
}

#define ZPITCH 68

__global__ __launch_bounds__(256, 2)
void lstm_step_fused(int t)
{
    const int m0 = blockIdx.y * 64;
    if (m0 >= g_nact[t]) return;

    extern __shared__ char smem_raw[];
    const uint32_t SM = smem_u32(smem_raw);
    float* zs = (float*)smem_raw;
    const int tid  = threadIdx.x;
    const int lane = tid & 31;
    const int wid  = tid >> 5;
    const int wm   = wid & 1;
    const int wn   = wid >> 1;
    const int n0 = blockIdx.x * 64;     // interleaved gate-col offset (BN=64)

    const h16* __restrict__ h_rd = g_h16[t & 1] + (size_t)m0 * HH;
    h16* __restrict__ h_wr = g_h16[(t + 1) & 1];

    float acc[2][2][4];
#pragma unroll
    for (int a = 0; a < 2; a++)
#pragma unroll
        for (int b = 0; b < 2; b++)
#pragma unroll
            for (int cc = 0; cc < 4; cc++) acc[a][b][cc] = 0.0f;

    gemm_mainloop<2, 2, 1, 3, false>(SM, h_rd, nullptr, g_wh_hi, nullptr,
                                     n0, HH, tid, acc);

    __syncthreads();

    // acc -> smem z tile (64 x 64)
    const int colq = (lane & 3) * 2;
    const int rowq = lane >> 2;
#pragma unroll
    for (int nt = 0; nt < 2; nt++) {
        const int col = wn * 16 + nt * 8 + colq;
#pragma unroll
        for (int mt = 0; mt < 2; mt++) {
            const int r0 = wm * 32 + mt * 16 + rowq;
            *(float2*)&zs[r0 * ZPITCH + col] = make_float2(acc[mt][nt][0], acc[mt][nt][1]);
            *(float2*)&zs[(r0 + 8) * ZPITCH + col] = make_float2(acc[mt][nt][2], acc[mt][nt][3]);
        }
    }
    __syncthreads();

    // cell epilogue: 64 rows x 16 units
#pragma unroll
    for (int i = 0; i < 4; i++) {
        const int idx = i * 256 + tid;
        const int r = idx >> 4;
        const int u = idx & 15;
        const int b = m0 + r;
        const int hx = (n0 >> 2) + u;

        float4 z4 = *(float4*)&zs[r * ZPITCH + 4 * u];
        float4 x4 = *(const float4*)(g_xw + ((size_t)b * TT + t) * FOURH + n0 + 4 * u);

        const float zi = z4.x + x4.x;
        const float zj = z4.y + x4.y;
        const float zf = z4.z + x4.z;
        const float zo = z4.w + x4.w;

        const size_t si = (size_t)b * HH + hx;
        const float c = g_c[si];
        const float hprev = g_h[si];
        const bool m = t < g_seqp[b];

        const float nc = c * sigf(zf + 1.0f) + sigf(zi) * tanhf(zj);
        const float nh = tanhf(nc) * sigf(zo);

        const float co = m ? nc : c;
        const float ho = m ? nh : hprev;
        const float fe = m ? nh : 0.0f;

        g_c[si] = co;
        g_h[si] = ho;
        h_wr[si] = __float2half(ho);
        g_f16[((size_t)b * TT + t) * HH + hx] = __float2half(fe);
    }
}

// ---------------------------------------------------------------------------
// Prep kernels
// ---------------------------------------------------------------------------
__global__ void sort_batches(const int* __restrict__ seq)
{
    __shared__ int hist[130];
    __shared__ int off[130];
    const int tid = threadIdx.x;
    if (tid < 130) hist[tid] = 0;
    __syncthreads();
    for (int b = tid; b < BB; b += 256) atomicAdd(&hist[seq[b]], 1);
    __syncthreads();
    if (tid == 0) {
        int acc = 0;
        for (int v = 128; v >= 1; v--) { off[v] = acc; acc += hist[v]; }
    }
    __syncthreads();
    if (tid < TT) g_nact[tid] = (tid == 0) ? BB : off[tid];   // #seq > t
    __syncthreads();
    if (tid == 0) {
        for (int b = 0; b < BB; b++) {
            const int v = seq[b];
            const int p = off[v]++;
            g_perm[p] = b;
            g_seqp[p] = v;
        }
        int acc = 0;
        for (int b = 0; b < BB; b++) { g_rowoff[b] = acc; acc += g_seqp[b]; }
        g_total[0] = acc;
    }
}

__global__ void fill_rows()
{
    const int bp = blockIdx.x;
    const int s = g_seqp[bp];
    const int off = g_rowoff[bp];
    const int dst0 = bp * TT;
    const int src0 = g_perm[bp] * TT;
    for (int t = threadIdx.x; t < s; t += 128) {
        g_rows[off + t] = dst0 + t;
        g_rowsrc[off + t] = src0 + t;
    }
    if (bp == 0 && threadIdx.x < 128) {      // pad tail tile with safe row 0
        const int total = g_total[0];
        g_rows[total + threadIdx.x] = 0;
        g_rowsrc[total + threadIdx.x] = 0;
    }
}

__global__ void init_state(const float* __restrict__ c_in, const float* __restrict__ h_in)
{
    int i = blockIdx.x * blockDim.x + threadIdx.x;
    if (i < BB * HH) {
        const int bp = i / HH;
        const int hx = i - bp * HH;
        const size_t src = (size_t)g_perm[bp] * HH + hx;
        g_c[i] = c_in[src];
        float h = h_in[src];
        g_h[i] = h;
        g_h16[0][i] = __float2half(h);
    }
}

// Convert only ACTIVE rows of X (one packed row per block of 128 threads).
__global__ __launch_bounds__(128) void convert_x_packed(const float* __restrict__ x)
{
    const int p = blockIdx.x;
    if (p >= g_total[0]) return;
    const size_t row = (size_t)g_rowsrc[p] * FF;
    const int t4 = threadIdx.x * 8;          // 8 elems per thread
    float4 v0 = *(const float4*)(x + row + t4);
    float4 v1 = *(const float4*)(x + row + t4 + 4);
    union { h16 h[8]; uint4 u; } H;
    H.h[0] = __float2half(v0.x); H.h[1] = __float2half(v0.y);
    H.h[2] = __float2half(v0.z); H.h[3] = __float2half(v0.w);
    H.h[4] = __float2half(v1.x); H.h[5] = __float2half(v1.y);
    H.h[6] = __float2half(v1.z); H.h[7] = __float2half(v1.w);
    *(uint4*)(g_x16 + row + t4) = H.u;
}

__global__ void transpose_split(const float* __restrict__ in, h16* __restrict__ oh,
                                h16* __restrict__ ol, int K, int N, int interleave)
{
    __shared__ float tile[32][33];
    const int kb = blockIdx.y * 32;
    const int nb = blockIdx.x * 32;
    const int tx = threadIdx.x;
    for (int r = threadIdx.y; r < 32; r += 8)
        tile[r][tx] = in[(size_t)(kb + r) * N + nb + tx];
    __syncthreads();
    for (int rr = threadIdx.y; rr < 32; rr += 8) {
        float v = tile[tx][rr];
        h16 hi, lo;
        splitw(v, hi, lo);
        int c = nb + rr;
        int n_new = interleave ? ((c & 1023) * 4 + (c >> 10)) : c;
        const size_t o = (size_t)n_new * K + kb + tx;
        oh[o] = hi;
        if (ol) ol[o] = lo;
    }
}

__global__ void permute_bias(const float* __restrict__ b)
{
    int c = blockIdx.x * 256 + threadIdx.x;
    if (c < FOURH) g_bias[(c & 1023) * 4 + (c >> 10)] = b[c];
}

// ---------------------------------------------------------------------------
// kernel_launch
// ---------------------------------------------------------------------------
extern "C" void kernel_launch(void* const* d_in, const int* in_sizes, int n_in,
                              void* d_out, int out_size)
{
    const float* X    = (const float*)d_in[0];
    const int*   seq  = (const int*)d_in[1];
    const float* c_in = (const float*)d_in[2];
    const float* h_in = (const float*)d_in[3];
    const float* W    = (const float*)d_in[4];
    const float* bias = (const float*)d_in[5];
    const float* Wout = (const float*)d_in[6];
    const float* bout = (const float*)d_in[7];
    float* out = (float*)d_out;

    h16 *p_wxh, *p_whh, *p_woh;
    cudaGetSymbolAddress((void**)&p_wxh, g_wx_hi);
    cudaGetSymbolAddress((void**)&p_whh, g_wh_hi);
    cudaGetSymbolAddress((void**)&p_woh, g_wo_hi);

    cudaFuncSetAttribute(gemm_xw_packed, cudaFuncAttributeMaxDynamicSharedMemorySize, SMEM_X);
    cudaFuncSetAttribute(gemm_head_packed, cudaFuncAttributeMaxDynamicSharedMemorySize, SMEM_H);
    cudaFuncSetAttribute(lstm_step_fused, cudaFuncAttributeMaxDynamicSharedMemorySize, SMEM_REC);

    // prep
    sort_batches<<<1, 256>>>(seq);
    fill_rows<<<BB, 128>>>();
    init_state<<<(BB * HH + 255) / 256, 256>>>(c_in, h_in);
    convert_x_packed<<<BT, 128>>>(X);
    transpose_split<<<dim3(FOURH / 32, FF / 32), dim3(32, 8)>>>(W, p_wxh, nullptr, FF, FOURH, 1);
    transpose_split<<<dim3(FOURH / 32, HH / 32), dim3(32, 8)>>>(W + (size_t)FF * FOURH, p_whh, nullptr, HH, FOURH, 1);
    transpose_split<<<dim3(NOUT / 32, HH / 32), dim3(32, 8)>>>(Wout, p_woh, nullptr, HH, NOUT, 0);
    permute_bias<<<FOURH / 256, 256>>>(bias);

    // XW over packed active rows (BM=128)
    gemm_xw_packed<<<dim3(FOURH / 128, BT / 128), 256, SMEM_X>>>();

    // recurrence: per-step launches, BM=64/BN=64 tiles, single-term Wh
    for (int t = 0; t < TT; t++)
        lstm_step_fused<<<dim3(FOURH / 64, BB / 64), 256, SMEM_REC>>>(t);

    // head over packed active rows + bias fill for inactive rows
    head_bias_fill<<<BB, 256>>>(bout, out);
    gemm_head_packed<<<dim3(NOUT / 128, BT / 64), 256, SMEM_H>>>(bout, out);
}

// round 15
// speedup vs baseline: 1.3381x; 1.3381x over previous
#include <cuda_runtime.h>
#include <cuda_fp16.h>
#include <math.h>
#include <stdint.h>

#define BB 512
#define TT 128
#define FF 1024
#define HH 1024
#define NOUT 256
#define FOURH 4096
#define BT 65536

typedef __half h16;

// ---------------------------------------------------------------------------
// Device-global scratch (sorted-batch order unless noted)
// ---------------------------------------------------------------------------
__device__ float g_xw[(size_t)BT * FOURH];     // X @ Wx + b, gate-interleaved cols
__device__ float g_c[BB * HH];
__device__ float g_h[BB * HH];
__device__ float g_bias[FOURH];                // permuted bias
__device__ h16   g_x16[(size_t)BT * FF];       // X as fp16 (ORIGINAL batch order; active rows only)
__device__ h16   g_f16[(size_t)BT * HH];       // masked h outputs (zero-init; inactive rows never written)
__device__ h16   g_h16[2][BB * HH];            // double-buffered h state, fp16
__device__ h16   g_wx_hi[(size_t)FOURH * FF];  // Wx^T [4H,F] K-major, interleaved rows
__device__ h16   g_wh_hi[(size_t)FOURH * HH];  // Wh^T (single fp16 term)
__device__ h16   g_wo_hi[NOUT * HH];
__device__ int   g_perm[BB];                   // sorted idx -> original idx
__device__ int   g_seqp[BB];                   // seq_len in sorted order (descending)
__device__ int   g_nact[TT];                   // #batches with seq_len > t
__device__ int   g_rowoff[BB];                 // prefix sum of seqp
__device__ int   g_total[1];                   // total active rows
__device__ int   g_rows[BT + 128];             // packed i -> sorted flat row (bp*TT+t)
__device__ int   g_rowsrc[BT + 128];           // packed i -> original flat row (perm[bp]*TT+t)

// ---------------------------------------------------------------------------
// Baseline-PTX helpers (legal on plain sm_103 target)
// ---------------------------------------------------------------------------
__device__ __forceinline__ uint32_t smem_u32(const void* p) {
    uint32_t a;
    asm("{ .reg .u64 t; cvta.to.shared.u64 t, %1; cvt.u32.u64 %0, t; }"
        : "=r"(a) : "l"(p));
    return a;
}
__device__ __forceinline__ void cp16(uint32_t dst, const void* src) {
    asm volatile("cp.async.cg.shared.global [%0], [%1], 16;"
                 :: "r"(dst), "l"(src) : "memory");
}
__device__ __forceinline__ void ldsm4(uint32_t* r, uint32_t addr) {
    asm volatile("ldmatrix.sync.aligned.m8n8.x4.shared.b16 {%0,%1,%2,%3}, [%4];"
                 : "=r"(r[0]), "=r"(r[1]), "=r"(r[2]), "=r"(r[3]) : "r"(addr));
}
__device__ __forceinline__ void mma16816(float* d, const uint32_t* a, const uint32_t* b) {
    asm volatile(
        "mma.sync.aligned.m16n8k16.row.col.f32.f16.f16.f32 "
        "{%0,%1,%2,%3}, {%4,%5,%6,%7}, {%8,%9}, {%0,%1,%2,%3};"
        : "+f"(d[0]), "+f"(d[1]), "+f"(d[2]), "+f"(d[3])
        : "r"(a[0]), "r"(a[1]), "r"(a[2]), "r"(a[3]), "r"(b[0]), "r"(b[1]));
}

// ---------------------------------------------------------------------------
// GEMM tile machinery. BM=MT*32 rows, BN=NT*32 cols, BK=32, 256 threads
// (8 warps: 2 row-groups x 4 col-groups). NB = B terms. NST = stages.
// PACKED: A rows gathered through an index array.
// ---------------------------------------------------------------------------
#define ROWB 80

template <int MT, int NT, int NB, bool PACKED>
__device__ __forceinline__ void load_stage(
    uint32_t stg, const h16* __restrict__ A, const int* __restrict__ aidx,
    const h16* __restrict__ Bh, const h16* __restrict__ Bl,
    int n0, int k0, int K, int tid)
{
    constexpr int BM = MT * 32;
    constexpr int BN = NT * 32;
    constexpr uint32_t OFFB = (uint32_t)BM * ROWB;
    constexpr uint32_t BTERM = (uint32_t)BN * ROWB;
#pragma unroll
    for (int i = 0; i < BM * 4 / 256; i++) {
        const int c = tid + i * 256;
        const int row = c >> 2;
        const int seg = c & 3;
        const h16* src = PACKED ? A + (size_t)aidx[row] * K + k0 + seg * 8
                                : A + (size_t)row * K + k0 + seg * 8;
        cp16(stg + (uint32_t)(row * ROWB + seg * 16), src);
    }
#pragma unroll
    for (int i = 0; i < BN * 4 / 256; i++) {
        const int c = tid + i * 256;
        const int row = c >> 2;
        const int seg = c & 3;
        const uint32_t soff = (uint32_t)(row * ROWB + seg * 16);
        const size_t gb = (size_t)(n0 + row) * K + k0 + seg * 8;
        cp16(stg + OFFB + soff, Bh + gb);
        if (NB == 2) cp16(stg + OFFB + BTERM + soff, Bl + gb);
    }
}

template <int MT, int NT, int NB, int NST, bool PACKED>
__device__ __forceinline__ void gemm_mainloop(
    uint32_t SM, const h16* __restrict__ A, const int* __restrict__ aidx,
    const h16* __restrict__ Bh, const h16* __restrict__ Bl,
    int n0, int K, int tid, float acc[MT][NT][4])
{
    constexpr int BM = MT * 32;
    constexpr int BN = NT * 32;
    constexpr uint32_t OFFB = (uint32_t)BM * ROWB;
    constexpr uint32_t BTERM = (uint32_t)BN * ROWB;
    constexpr uint32_t STG_B = OFFB + NB * BTERM;
    const int lane = tid & 31;
    const int wid  = tid >> 5;
    const int wm   = wid & 1;
    const int wn   = wid >> 1;
    const int NC = K >> 5;

#pragma unroll
    for (int s = 0; s < NST - 1; s++) {
        load_stage<MT, NT, NB, PACKED>(SM + s * STG_B, A, aidx, Bh, Bl, n0, s * 32, K, tid);
        asm volatile("cp.async.commit_group;" ::: "memory");
    }

    const int arow = wm * (MT * 16) + (lane & 15);
    const uint32_t akoff = (uint32_t)((lane >> 4) * 16);
    const int bsel = lane >> 3;
    const int bn = wn * (NT * 8) + ((bsel >> 1) << 3) + (lane & 7);
    const uint32_t bkoff = (uint32_t)((bsel & 1) * 16);

    for (int it = 0; it < NC; it++) {
        asm volatile("cp.async.wait_group %0;" :: "n"(NST - 2) : "memory");
        __syncthreads();

        const int nx = it + NST - 1;
        if (nx < NC)
            load_stage<MT, NT, NB, PACKED>(SM + (uint32_t)(nx % NST) * STG_B,
                                           A, aidx, Bh, Bl, n0, nx * 32, K, tid);
        asm volatile("cp.async.commit_group;" ::: "memory");

        const uint32_t stg = SM + (uint32_t)(it % NST) * STG_B;
#pragma unroll
        for (int ks = 0; ks < 2; ks++) {
            uint32_t ah[MT][4], bh[NT][2], bl[NT][2];
            const uint32_t ak = (uint32_t)(ks * 32) + akoff;
#pragma unroll
            for (int mt = 0; mt < MT; mt++)
                ldsm4(ah[mt], stg + (uint32_t)((arow + mt * 16) * ROWB) + ak);
            const uint32_t bk = (uint32_t)(ks * 32) + bkoff;
#pragma unroll
            for (int np = 0; np < NT / 2; np++) {
                const uint32_t bd = stg + OFFB + (uint32_t)((bn + np * 16) * ROWB) + bk;
                uint32_t tr[4];
                ldsm4(tr, bd);
                bh[2 * np][0] = tr[0]; bh[2 * np][1] = tr[1];
                bh[2 * np + 1][0] = tr[2]; bh[2 * np + 1][1] = tr[3];
                if (NB == 2) {
                    ldsm4(tr, bd + BTERM);
                    bl[2 * np][0] = tr[0]; bl[2 * np][1] = tr[1];
                    bl[2 * np + 1][0] = tr[2]; bl[2 * np + 1][1] = tr[3];
                }
            }
#pragma unroll
            for (int mt = 0; mt < MT; mt++)
#pragma unroll
                for (int nt = 0; nt < NT; nt++) {
                    mma16816(acc[mt][nt], ah[mt], bh[nt]);
                    if (NB == 2) mma16816(acc[mt][nt], ah[mt], bl[nt]);
                }
        }
    }
}

// Scatter epilogue: per-row destination via rows[], valid rows only (+bias).
template <int MT, int NT>
__device__ __forceinline__ void store_scatter(
    float acc[MT][NT][4], float* __restrict__ Cbase, const int* __restrict__ rows,
    const float* __restrict__ bias, int N, int n0, int tid, int nvalid)
{
    const int lane = tid & 31;
    const int wid  = tid >> 5;
    const int wm   = wid & 1;
    const int wn   = wid >> 1;
    const int colq = (lane & 3) * 2;
    const int rowq = lane >> 2;
    float bx[NT], by[NT];
#pragma unroll
    for (int nt = 0; nt < NT; nt++) {
        const int col = wn * (NT * 8) + nt * 8 + colq;
        float2 bv = *(const float2*)(bias + n0 + col);
        bx[nt] = bv.x; by[nt] = bv.y;
    }
#pragma unroll
    for (int mt = 0; mt < MT; mt++) {
        const int r0 = wm * (MT * 16) + mt * 16 + rowq;
#pragma unroll
        for (int half = 0; half < 2; half++) {
            const int rloc = r0 + half * 8;
            if (rloc < nvalid) {
                float* C = Cbase + (size_t)rows[rloc] * N;
#pragma unroll
                for (int nt = 0; nt < NT; nt++) {
                    const int col = wn * (NT * 8) + nt * 8 + colq;
                    *(float2*)(C + n0 + col) =
                        make_float2(acc[mt][nt][2 * half] + bx[nt],
                                    acc[mt][nt][2 * half + 1] + by[nt]);
                }
            }
        }
    }
}

// ---------------------------------------------------------------------------
// Packed XW GEMM: BM=128 (MT=4), NT=4, 4 stages, single weight term.
// ---------------------------------------------------------------------------
#define SMEM_X (4 * (128 * ROWB + 128 * ROWB))   // 81920
__global__ __launch_bounds__(256, 2)
void gemm_xw_packed()
{
    const int ts = blockIdx.y * 128;
    const int total = g_total[0];
    if (ts >= total) return;
    extern __shared__ char smem_raw[];
    const uint32_t SM = smem_u32(smem_raw);
    const int tid = threadIdx.x;
    const int n0 = blockIdx.x * 128;

    float acc[4][4][4];
#pragma unroll
    for (int a = 0; a < 4; a++)
#pragma unroll
        for (int b = 0; b < 4; b++)
#pragma unroll
            for (int cc = 0; cc < 4; cc++) acc[a][b][cc] = 0.0f;

    gemm_mainloop<4, 4, 1, 4, true>(SM, g_x16, g_rowsrc + ts, g_wx_hi, nullptr,
                                    n0, FF, tid, acc);
    store_scatter<4, 4>(acc, g_xw, g_rows + ts, g_bias, FOURH, n0, tid, total - ts);
}

// ---------------------------------------------------------------------------
// Packed head GEMM: BM=64 tiles (MT=2).
// ---------------------------------------------------------------------------
#define SMEM_H (4 * (64 * ROWB + 128 * ROWB))    // 61440
__global__ __launch_bounds__(256, 2)
void gemm_head_packed(const float* __restrict__ bout, float* __restrict__ out)
{
    const int ts = blockIdx.y * 64;
    const int total = g_total[0];
    if (ts >= total) return;
    extern __shared__ char smem_raw[];
    const uint32_t SM = smem_u32(smem_raw);
    const int tid = threadIdx.x;
    const int n0 = blockIdx.x * 128;

    float acc[2][4][4];
#pragma unroll
    for (int a = 0; a < 2; a++)
#pragma unroll
        for (int b = 0; b < 4; b++)
#pragma unroll
            for (int cc = 0; cc < 4; cc++) acc[a][b][cc] = 0.0f;

    gemm_mainloop<2, 4, 1, 4, true>(SM, g_f16, g_rows + ts, g_wo_hi, nullptr,
                                    n0, HH, tid, acc);
    store_scatter<2, 4>(acc, out, g_rowsrc + ts, bout, NOUT, n0, tid, total - ts);
}

// Bias fill for inactive head rows (logits = bias there).
__global__ void head_bias_fill(const float* __restrict__ bout, float* __restrict__ out)
{
    const int bp = blockIdx.x;
    const int s = g_seqp[bp];
    const int nrows = TT - s;
    if (nrows <= 0) return;
    const size_t base = ((size_t)g_perm[bp] * TT + s) * NOUT;
    for (int i = threadIdx.x; i < nrows * 64; i += 256) {
        const int r = i >> 6;
        const int c = (i & 63) * 4;
        *(float4*)(out + base + (size_t)r * NOUT + c) = *(const float4*)(bout + c);
    }
}

// ---------------------------------------------------------------------------
// Fused recurrent step: BM=64, BN=128 (NT=4), single-term Wh, 3 stages.
// Grid (32, 8) = 256 CTAs -> single wave at full activity with 2-CTA occupancy.
// ---------------------------------------------------------------------------
#define SMEM_REC (3 * (64 * ROWB + 128 * ROWB))   // 46080
__device__ __forceinline__ float sigf(float x) { return 1.0f / (1.0f + expf(-x)); }
__device__ __forceinline__ void splitw(float v, h16& hi, h16& lo) {
    hi = __float2half(v);
    lo = __float2half(v - __half2float(hi));
}

#define ZPITCH 132

__global__ __launch_bounds__(256, 2)
void lstm_step_fused(int t)
{
    const int m0 = blockIdx.y * 64;
    if (m0 >= g_nact[t]) return;

    extern __shared__ char smem_raw[];
    const uint32_t SM = smem_u32(smem_raw);
    float* zs = (float*)smem_raw;
    const int tid  = threadIdx.x;
    const int lane = tid & 31;
    const int wid  = tid >> 5;
    const int wm   = wid & 1;
    const int wn   = wid >> 1;
    const int n0 = blockIdx.x * 128;    // interleaved gate-col offset (BN=128)

    const h16* __restrict__ h_rd = g_h16[t & 1] + (size_t)m0 * HH;
    h16* __restrict__ h_wr = g_h16[(t + 1) & 1];

    float acc[2][4][4];
#pragma unroll
    for (int a = 0; a < 2; a++)
#pragma unroll
        for (int b = 0; b < 4; b++)
#pragma unroll
            for (int cc = 0; cc < 4; cc++) acc[a][b][cc] = 0.0f;

    gemm_mainloop<2, 4, 1, 3, false>(SM, h_rd, nullptr, g_wh_hi, nullptr,
                                     n0, HH, tid, acc);

    __syncthreads();

    // acc -> smem z tile (64 x 128)
    const int colq = (lane & 3) * 2;
    const int rowq = lane >> 2;
#pragma unroll
    for (int nt = 0; nt < 4; nt++) {
        const int col = wn * 32 + nt * 8 + colq;
#pragma unroll
        for (int mt = 0; mt < 2; mt++) {
            const int r0 = wm * 32 + mt * 16 + rowq;
            *(float2*)&zs[r0 * ZPITCH + col] = make_float2(acc[mt][nt][0], acc[mt][nt][1]);
            *(float2*)&zs[(r0 + 8) * ZPITCH + col] = make_float2(acc[mt][nt][2], acc[mt][nt][3]);
        }
    }
    __syncthreads();

    // cell epilogue: 64 rows x 32 units
#pragma unroll
    for (int i = 0; i < 8; i++) {
        const int idx = i * 256 + tid;
        const int r = idx >> 5;
        const int u = idx & 31;
        const int b = m0 + r;
        const int hx = (n0 >> 2) + u;

        float4 z4 = *(float4*)&zs[r * ZPITCH + 4 * u];
        float4 x4 = *(const float4*)(g_xw + ((size_t)b * TT + t) * FOURH + n0 + 4 * u);

        const float zi = z4.x + x4.x;
        const float zj = z4.y + x4.y;
        const float zf = z4.z + x4.z;
        const float zo = z4.w + x4.w;

        const size_t si = (size_t)b * HH + hx;
        const float c = g_c[si];
        const float hprev = g_h[si];
        const bool m = t < g_seqp[b];

        const float nc = c * sigf(zf + 1.0f) + sigf(zi) * tanhf(zj);
        const float nh = tanhf(nc) * sigf(zo);

        const float co = m ? nc : c;
        const float ho = m ? nh : hprev;
        const float fe = m ? nh : 0.0f;

        g_c[si] = co;
        g_h[si] = ho;
        h_wr[si] = __float2half(ho);
        g_f16[((size_t)b * TT + t) * HH + hx] = __float2half(fe);
    }
}

// ---------------------------------------------------------------------------
// Prep kernels
// ---------------------------------------------------------------------------
__global__ void sort_batches(const int* __restrict__ seq)
{
    __shared__ int hist[130];
    __shared__ int off[130];
    const int tid = threadIdx.x;
    if (tid < 130) hist[tid] = 0;
    __syncthreads();
    for (int b = tid; b < BB; b += 256) atomicAdd(&hist[seq[b]], 1);
    __syncthreads();
    if (tid == 0) {
        int acc = 0;
        for (int v = 128; v >= 1; v--) { off[v] = acc; acc += hist[v]; }
    }
    __syncthreads();
    if (tid < TT) g_nact[tid] = (tid == 0) ? BB : off[tid];   // #seq > t
    __syncthreads();
    if (tid == 0) {
        for (int b = 0; b < BB; b++) {
            const int v = seq[b];
            const int p = off[v]++;
            g_perm[p] = b;
            g_seqp[p] = v;
        }
        int acc = 0;
        for (int b = 0; b < BB; b++) { g_rowoff[b] = acc; acc += g_seqp[b]; }
        g_total[0] = acc;
    }
}

__global__ void fill_rows()
{
    const int bp = blockIdx.x;
    const int s = g_seqp[bp];
    const int off = g_rowoff[bp];
    const int dst0 = bp * TT;
    const int src0 = g_perm[bp] * TT;
    for (int t = threadIdx.x; t < s; t += 128) {
        g_rows[off + t] = dst0 + t;
        g_rowsrc[off + t] = src0 + t;
    }
    if (bp == 0 && threadIdx.x < 128) {      // pad tail tile with safe row 0
        const int total = g_total[0];
        g_rows[total + threadIdx.x] = 0;
        g_rowsrc[total + threadIdx.x] = 0;
    }
}

__global__ void init_state(const float* __restrict__ c_in, const float* __restrict__ h_in)
{
    int i = blockIdx.x * blockDim.x + threadIdx.x;
    if (i < BB * HH) {
        const int bp = i / HH;
        const int hx = i - bp * HH;
        const size_t src = (size_t)g_perm[bp] * HH + hx;
        g_c[i] = c_in[src];
        float h = h_in[src];
        g_h[i] = h;
        g_h16[0][i] = __float2half(h);
    }
}

// Convert only ACTIVE rows of X (one packed row per block of 128 threads).
__global__ __launch_bounds__(128) void convert_x_packed(const float* __restrict__ x)
{
    const int p = blockIdx.x;
    if (p >= g_total[0]) return;
    const size_t row = (size_t)g_rowsrc[p] * FF;
    const int t4 = threadIdx.x * 8;          // 8 elems per thread
    float4 v0 = *(const float4*)(x + row + t4);
    float4 v1 = *(const float4*)(x + row + t4 + 4);
    union { h16 h[8]; uint4 u; } H;
    H.h[0] = __float2half(v0.x); H.h[1] = __float2half(v0.y);
    H.h[2] = __float2half(v0.z); H.h[3] = __float2half(v0.w);
    H.h[4] = __float2half(v1.x); H.h[5] = __float2half(v1.y);
    H.h[6] = __float2half(v1.z); H.h[7] = __float2half(v1.w);
    *(uint4*)(g_x16 + row + t4) = H.u;
}

__global__ void transpose_split(const float* __restrict__ in, h16* __restrict__ oh,
                                h16* __restrict__ ol, int K, int N, int interleave)
{
    __shared__ float tile[32][33];
    const int kb = blockIdx.y * 32;
    const int nb = blockIdx.x * 32;
    const int tx = threadIdx.x;
    for (int r = threadIdx.y; r < 32; r += 8)
        tile[r][tx] = in[(size_t)(kb + r) * N + nb + tx];
    __syncthreads();
    for (int rr = threadIdx.y; rr < 32; rr += 8) {
        float v = tile[tx][rr];
        h16 hi, lo;
        splitw(v, hi, lo);
        int c = nb + rr;
        int n_new = interleave ? ((c & 1023) * 4 + (c >> 10)) : c;
        const size_t o = (size_t)n_new * K + kb + tx;
        oh[o] = hi;
        if (ol) ol[o] = lo;
    }
}

__global__ void permute_bias(const float* __restrict__ b)
{
    int c = blockIdx.x * 256 + threadIdx.x;
    if (c < FOURH) g_bias[(c & 1023) * 4 + (c >> 10)] = b[c];
}

// ---------------------------------------------------------------------------
// kernel_launch
// ---------------------------------------------------------------------------
extern "C" void kernel_launch(void* const* d_in, const int* in_sizes, int n_in,
                              void* d_out, int out_size)
{
    const float* X    = (const float*)d_in[0];
    const int*   seq  = (const int*)d_in[1];
    const float* c_in = (const float*)d_in[2];
    const float* h_in = (const float*)d_in[3];
    const float* W    = (const float*)d_in[4];
    const float* bias = (const float*)d_in[5];
    const float* Wout = (const float*)d_in[6];
    const float* bout = (const float*)d_in[7];
    float* out = (float*)d_out;

    h16 *p_wxh, *p_whh, *p_woh;
    cudaGetSymbolAddress((void**)&p_wxh, g_wx_hi);
    cudaGetSymbolAddress((void**)&p_whh, g_wh_hi);
    cudaGetSymbolAddress((void**)&p_woh, g_wo_hi);

    cudaFuncSetAttribute(gemm_xw_packed, cudaFuncAttributeMaxDynamicSharedMemorySize, SMEM_X);
    cudaFuncSetAttribute(gemm_head_packed, cudaFuncAttributeMaxDynamicSharedMemorySize, SMEM_H);
    cudaFuncSetAttribute(lstm_step_fused, cudaFuncAttributeMaxDynamicSharedMemorySize, SMEM_REC);

    // prep
    sort_batches<<<1, 256>>>(seq);
    fill_rows<<<BB, 128>>>();
    init_state<<<(BB * HH + 255) / 256, 256>>>(c_in, h_in);
    convert_x_packed<<<BT, 128>>>(X);
    transpose_split<<<dim3(FOURH / 32, FF / 32), dim3(32, 8)>>>(W, p_wxh, nullptr, FF, FOURH, 1);
    transpose_split<<<dim3(FOURH / 32, HH / 32), dim3(32, 8)>>>(W + (size_t)FF * FOURH, p_whh, nullptr, HH, FOURH, 1);
    transpose_split<<<dim3(NOUT / 32, HH / 32), dim3(32, 8)>>>(Wout, p_woh, nullptr, HH, NOUT, 0);
    permute_bias<<<FOURH / 256, 256>>>(bias);

    // XW over packed active rows (BM=128)
    gemm_xw_packed<<<dim3(FOURH / 128, BT / 128), 256, SMEM_X>>>();

    // recurrence: per-step launches, BM=64/BN=128 tiles, single-term Wh
    for (int t = 0; t < TT; t++)
        lstm_step_fused<<<dim3(FOURH / 128, BB / 64), 256, SMEM_REC>>>(t);

    // head over packed active rows + bias fill for inactive rows
    head_bias_fill<<<BB, 256>>>(bout, out);
    gemm_head_packed<<<dim3(NOUT / 128, BT / 64), 256, SMEM_H>>>(bout, out);
}

// round 16
// speedup vs baseline: 1.4098x; 1.0536x over previous
#include <cuda_runtime.h>
#include <cuda_fp16.h>
#include <math.h>
#include <stdint.h>

#define BB 512
#define TT 128
#define FF 1024
#define HH 1024
#define NOUT 256
#define FOURH 4096
#define BT 65536

typedef __half h16;

// ---------------------------------------------------------------------------
// Device-global scratch (sorted-batch order unless noted)
// ---------------------------------------------------------------------------
__device__ h16   g_xw16[(size_t)BT * FOURH];   // X @ Wx + b, gate-interleaved cols (fp16)
__device__ float g_c[BB * HH];
__device__ float g_h[BB * HH];
__device__ float g_bias[FOURH];                // permuted bias
__device__ h16   g_x16[(size_t)BT * FF];       // X as fp16 (ORIGINAL batch order; active rows only)
__device__ h16   g_f16[(size_t)BT * HH];       // masked h outputs (zero-init; inactive rows never written)
__device__ h16   g_h16[2][BB * HH];            // double-buffered h state, fp16
__device__ h16   g_wx_hi[(size_t)FOURH * FF];  // Wx^T [4H,F] K-major, interleaved rows
__device__ h16   g_wh_hi[(size_t)FOURH * HH];  // Wh^T (single fp16 term)
__device__ h16   g_wo_hi[NOUT * HH];
__device__ int   g_perm[BB];                   // sorted idx -> original idx
__device__ int   g_seqp[BB];                   // seq_len in sorted order (descending)
__device__ int   g_nact[TT];                   // #batches with seq_len > t
__device__ int   g_rowoff[BB];                 // prefix sum of seqp
__device__ int   g_total[1];                   // total active rows
__device__ int   g_rows[BT + 128];             // packed i -> sorted flat row (bp*TT+t)
__device__ int   g_rowsrc[BT + 128];           // packed i -> original flat row (perm[bp]*TT+t)

// ---------------------------------------------------------------------------
// Baseline-PTX helpers (legal on plain sm_103 target)
// ---------------------------------------------------------------------------
__device__ __forceinline__ uint32_t smem_u32(const void* p) {
    uint32_t a;
    asm("{ .reg .u64 t; cvta.to.shared.u64 t, %1; cvt.u32.u64 %0, t; }"
        : "=r"(a) : "l"(p));
    return a;
}
__device__ __forceinline__ void cp16(uint32_t dst, const void* src) {
    asm volatile("cp.async.cg.shared.global [%0], [%1], 16;"
                 :: "r"(dst), "l"(src) : "memory");
}
__device__ __forceinline__ void ldsm4(uint32_t* r, uint32_t addr) {
    asm volatile("ldmatrix.sync.aligned.m8n8.x4.shared.b16 {%0,%1,%2,%3}, [%4];"
                 : "=r"(r[0]), "=r"(r[1]), "=r"(r[2]), "=r"(r[3]) : "r"(addr));
}
__device__ __forceinline__ void mma16816(float* d, const uint32_t* a, const uint32_t* b) {
    asm volatile(
        "mma.sync.aligned.m16n8k16.row.col.f32.f16.f16.f32 "
        "{%0,%1,%2,%3}, {%4,%5,%6,%7}, {%8,%9}, {%0,%1,%2,%3};"
        : "+f"(d[0]), "+f"(d[1]), "+f"(d[2]), "+f"(d[3])
        : "r"(a[0]), "r"(a[1]), "r"(a[2]), "r"(a[3]), "r"(b[0]), "r"(b[1]));
}

// ---------------------------------------------------------------------------
// GEMM tile machinery. BM=MT*32 rows, BN=NT*32 cols, BK=32, 256 threads
// (8 warps: 2 row-groups x 4 col-groups). NB = B terms. NST = stages.
// PACKED: A rows gathered through an index array.
// ---------------------------------------------------------------------------
#define ROWB 80

template <int MT, int NT, int NB, bool PACKED>
__device__ __forceinline__ void load_stage(
    uint32_t stg, const h16* __restrict__ A, const int* __restrict__ aidx,
    const h16* __restrict__ Bh, const h16* __restrict__ Bl,
    int n0, int k0, int K, int tid)
{
    constexpr int BM = MT * 32;
    constexpr int BN = NT * 32;
    constexpr uint32_t OFFB = (uint32_t)BM * ROWB;
    constexpr uint32_t BTERM = (uint32_t)BN * ROWB;
#pragma unroll
    for (int i = 0; i < BM * 4 / 256; i++) {
        const int c = tid + i * 256;
        const int row = c >> 2;
        const int seg = c & 3;
        const h16* src = PACKED ? A + (size_t)aidx[row] * K + k0 + seg * 8
                                : A + (size_t)row * K + k0 + seg * 8;
        cp16(stg + (uint32_t)(row * ROWB + seg * 16), src);
    }
#pragma unroll
    for (int i = 0; i < BN * 4 / 256; i++) {
        const int c = tid + i * 256;
        const int row = c >> 2;
        const int seg = c & 3;
        const uint32_t soff = (uint32_t)(row * ROWB + seg * 16);
        const size_t gb = (size_t)(n0 + row) * K + k0 + seg * 8;
        cp16(stg + OFFB + soff, Bh + gb);
        if (NB == 2) cp16(stg + OFFB + BTERM + soff, Bl + gb);
    }
}

template <int MT, int NT, int NB, int NST, bool PACKED>
__device__ __forceinline__ void gemm_mainloop(
    uint32_t SM, const h16* __restrict__ A, const int* __restrict__ aidx,
    const h16* __restrict__ Bh, const h16* __restrict__ Bl,
    int n0, int K, int tid, float acc[MT][NT][4])
{
    constexpr int BM = MT * 32;
    constexpr int BN = NT * 32;
    constexpr uint32_t OFFB = (uint32_t)BM * ROWB;
    constexpr uint32_t BTERM = (uint32_t)BN * ROWB;
    constexpr uint32_t STG_B = OFFB + NB * BTERM;
    const int lane = tid & 31;
    const int wid  = tid >> 5;
    const int wm   = wid & 1;
    const int wn   = wid >> 1;
    const int NC = K >> 5;

#pragma unroll
    for (int s = 0; s < NST - 1; s++) {
        load_stage<MT, NT, NB, PACKED>(SM + s * STG_B, A, aidx, Bh, Bl, n0, s * 32, K, tid);
        asm volatile("cp.async.commit_group;" ::: "memory");
    }

    const int arow = wm * (MT * 16) + (lane & 15);
    const uint32_t akoff = (uint32_t)((lane >> 4) * 16);
    const int bsel = lane >> 3;
    const int bn = wn * (NT * 8) + ((bsel >> 1) << 3) + (lane & 7);
    const uint32_t bkoff = (uint32_t)((bsel & 1) * 16);

    for (int it = 0; it < NC; it++) {
        asm volatile("cp.async.wait_group %0;" :: "n"(NST - 2) : "memory");
        __syncthreads();

        const int nx = it + NST - 1;
        if (nx < NC)
            load_stage<MT, NT, NB, PACKED>(SM + (uint32_t)(nx % NST) * STG_B,
                                           A, aidx, Bh, Bl, n0, nx * 32, K, tid);
        asm volatile("cp.async.commit_group;" ::: "memory");

        const uint32_t stg = SM + (uint32_t)(it % NST) * STG_B;
#pragma unroll
        for (int ks = 0; ks < 2; ks++) {
            uint32_t ah[MT][4], bh[NT][2], bl[NT][2];
            const uint32_t ak = (uint32_t)(ks * 32) + akoff;
#pragma unroll
            for (int mt = 0; mt < MT; mt++)
                ldsm4(ah[mt], stg + (uint32_t)((arow + mt * 16) * ROWB) + ak);
            const uint32_t bk = (uint32_t)(ks * 32) + bkoff;
#pragma unroll
            for (int np = 0; np < NT / 2; np++) {
                const uint32_t bd = stg + OFFB + (uint32_t)((bn + np * 16) * ROWB) + bk;
                uint32_t tr[4];
                ldsm4(tr, bd);
                bh[2 * np][0] = tr[0]; bh[2 * np][1] = tr[1];
                bh[2 * np + 1][0] = tr[2]; bh[2 * np + 1][1] = tr[3];
                if (NB == 2) {
                    ldsm4(tr, bd + BTERM);
                    bl[2 * np][0] = tr[0]; bl[2 * np][1] = tr[1];
                    bl[2 * np + 1][0] = tr[2]; bl[2 * np + 1][1] = tr[3];
                }
            }
#pragma unroll
            for (int mt = 0; mt < MT; mt++)
#pragma unroll
                for (int nt = 0; nt < NT; nt++) {
                    mma16816(acc[mt][nt], ah[mt], bh[nt]);
                    if (NB == 2) mma16816(acc[mt][nt], ah[mt], bl[nt]);
                }
        }
    }
}

// Scatter epilogue (fp32 out): per-row destination via rows[], valid rows only.
template <int MT, int NT>
__device__ __forceinline__ void store_scatter(
    float acc[MT][NT][4], float* __restrict__ Cbase, const int* __restrict__ rows,
    const float* __restrict__ bias, int N, int n0, int tid, int nvalid)
{
    const int lane = tid & 31;
    const int wid  = tid >> 5;
    const int wm   = wid & 1;
    const int wn   = wid >> 1;
    const int colq = (lane & 3) * 2;
    const int rowq = lane >> 2;
    float bx[NT], by[NT];
#pragma unroll
    for (int nt = 0; nt < NT; nt++) {
        const int col = wn * (NT * 8) + nt * 8 + colq;
        float2 bv = *(const float2*)(bias + n0 + col);
        bx[nt] = bv.x; by[nt] = bv.y;
    }
#pragma unroll
    for (int mt = 0; mt < MT; mt++) {
        const int r0 = wm * (MT * 16) + mt * 16 + rowq;
#pragma unroll
        for (int half = 0; half < 2; half++) {
            const int rloc = r0 + half * 8;
            if (rloc < nvalid) {
                float* C = Cbase + (size_t)rows[rloc] * N;
#pragma unroll
                for (int nt = 0; nt < NT; nt++) {
                    const int col = wn * (NT * 8) + nt * 8 + colq;
                    *(float2*)(C + n0 + col) =
                        make_float2(acc[mt][nt][2 * half] + bx[nt],
                                    acc[mt][nt][2 * half + 1] + by[nt]);
                }
            }
        }
    }
}

// Scatter epilogue (fp16 out) for g_xw16.
template <int MT, int NT>
__device__ __forceinline__ void store_scatter_h16(
    float acc[MT][NT][4], h16* __restrict__ Cbase, const int* __restrict__ rows,
    const float* __restrict__ bias, int N, int n0, int tid, int nvalid)
{
    const int lane = tid & 31;
    const int wid  = tid >> 5;
    const int wm   = wid & 1;
    const int wn   = wid >> 1;
    const int colq = (lane & 3) * 2;
    const int rowq = lane >> 2;
    float bx[NT], by[NT];
#pragma unroll
    for (int nt = 0; nt < NT; nt++) {
        const int col = wn * (NT * 8) + nt * 8 + colq;
        float2 bv = *(const float2*)(bias + n0 + col);
        bx[nt] = bv.x; by[nt] = bv.y;
    }
#pragma unroll
    for (int mt = 0; mt < MT; mt++) {
        const int r0 = wm * (MT * 16) + mt * 16 + rowq;
#pragma unroll
        for (int half = 0; half < 2; half++) {
            const int rloc = r0 + half * 8;
            if (rloc < nvalid) {
                h16* C = Cbase + (size_t)rows[rloc] * N;
#pragma unroll
                for (int nt = 0; nt < NT; nt++) {
                    const int col = wn * (NT * 8) + nt * 8 + colq;
                    __half2 hv = __floats2half2_rn(acc[mt][nt][2 * half] + bx[nt],
                                                   acc[mt][nt][2 * half + 1] + by[nt]);
                    *(__half2*)(C + n0 + col) = hv;
                }
            }
        }
    }
}

// ---------------------------------------------------------------------------
// Packed XW GEMM: BM=128 (MT=4), NT=4, 4 stages, single weight term, fp16 out.
// ---------------------------------------------------------------------------
#define SMEM_X (4 * (128 * ROWB + 128 * ROWB))   // 81920
__global__ __launch_bounds__(256, 2)
void gemm_xw_packed()
{
    const int ts = blockIdx.y * 128;
    const int total = g_total[0];
    if (ts >= total) return;
    extern __shared__ char smem_raw[];
    const uint32_t SM = smem_u32(smem_raw);
    const int tid = threadIdx.x;
    const int n0 = blockIdx.x * 128;

    float acc[4][4][4];
#pragma unroll
    for (int a = 0; a < 4; a++)
#pragma unroll
        for (int b = 0; b < 4; b++)
#pragma unroll
            for (int cc = 0; cc < 4; cc++) acc[a][b][cc] = 0.0f;

    gemm_mainloop<4, 4, 1, 4, true>(SM, g_x16, g_rowsrc + ts, g_wx_hi, nullptr,
                                    n0, FF, tid, acc);
    store_scatter_h16<4, 4>(acc, g_xw16, g_rows + ts, g_bias, FOURH, n0, tid, total - ts);
}

// ---------------------------------------------------------------------------
// Packed head GEMM: BM=64 tiles (MT=2).
// ---------------------------------------------------------------------------
#define SMEM_H (4 * (64 * ROWB + 128 * ROWB))    // 61440
__global__ __launch_bounds__(256, 2)
void gemm_head_packed(const float* __restrict__ bout, float* __restrict__ out)
{
    const int ts = blockIdx.y * 64;
    const int total = g_total[0];
    if (ts >= total) return;
    extern __shared__ char smem_raw[];
    const uint32_t SM = smem_u32(smem_raw);
    const int tid = threadIdx.x;
    const int n0 = blockIdx.x * 128;

    float acc[2][4][4];
#pragma unroll
    for (int a = 0; a < 2; a++)
#pragma unroll
        for (int b = 0; b < 4; b++)
#pragma unroll
            for (int cc = 0; cc < 4; cc++) acc[a][b][cc] = 0.0f;

    gemm_mainloop<2, 4, 1, 4, true>(SM, g_f16, g_rows + ts, g_wo_hi, nullptr,
                                    n0, HH, tid, acc);
    store_scatter<2, 4>(acc, out, g_rowsrc + ts, bout, NOUT, n0, tid, total - ts);
}

// Bias fill for inactive head rows (logits = bias there).
__global__ void head_bias_fill(const float* __restrict__ bout, float* __restrict__ out)
{
    const int bp = blockIdx.x;
    const int s = g_seqp[bp];
    const int nrows = TT - s;
    if (nrows <= 0) return;
    const size_t base = ((size_t)g_perm[bp] * TT + s) * NOUT;
    for (int i = threadIdx.x; i < nrows * 64; i += 256) {
        const int r = i >> 6;
        const int c = (i & 63) * 4;
        *(float4*)(out + base + (size_t)r * NOUT + c) = *(const float4*)(bout + c);
    }
}

// ---------------------------------------------------------------------------
// Fused recurrent step: BM=64, BN=128 (NT=4), single-term Wh, 4 stages.
// Grid (32, 8) = 256 CTAs -> single wave at full activity with 2-CTA occupancy.
// ---------------------------------------------------------------------------
#define SMEM_REC (4 * (64 * ROWB + 128 * ROWB))   // 61440
__device__ __forceinline__ float sigf(float x) { return 1.0f / (1.0f + expf(-x)); }
__device__ __forceinline__ void splitw(float v, h16& hi, h16& lo) {
    hi = __float2half(v);
    lo = __float2half(v - __half2float(hi));
}

#define ZPITCH 132

__global__ __launch_bounds__(256, 2)
void lstm_step_fused(int t)
{
    const int m0 = blockIdx.y * 64;
    if (m0 >= g_nact[t]) return;

    extern __shared__ char smem_raw[];
    const uint32_t SM = smem_u32(smem_raw);
    float* zs = (float*)smem_raw;
    const int tid  = threadIdx.x;
    const int lane = tid & 31;
    const int wid  = tid >> 5;
    const int wm   = wid & 1;
    const int wn   = wid >> 1;
    const int n0 = blockIdx.x * 128;    // interleaved gate-col offset (BN=128)

    const h16* __restrict__ h_rd = g_h16[t & 1] + (size_t)m0 * HH;
    h16* __restrict__ h_wr = g_h16[(t + 1) & 1];

    float acc[2][4][4];
#pragma unroll
    for (int a = 0; a < 2; a++)
#pragma unroll
        for (int b = 0; b < 4; b++)
#pragma unroll
            for (int cc = 0; cc < 4; cc++) acc[a][b][cc] = 0.0f;

    gemm_mainloop<2, 4, 1, 4, false>(SM, h_rd, nullptr, g_wh_hi, nullptr,
                                     n0, HH, tid, acc);

    __syncthreads();

    // acc -> smem z tile (64 x 128)
    const int colq = (lane & 3) * 2;
    const int rowq = lane >> 2;
#pragma unroll
    for (int nt = 0; nt < 4; nt++) {
        const int col = wn * 32 + nt * 8 + colq;
#pragma unroll
        for (int mt = 0; mt < 2; mt++) {
            const int r0 = wm * 32 + mt * 16 + rowq;
            *(float2*)&zs[r0 * ZPITCH + col] = make_float2(acc[mt][nt][0], acc[mt][nt][1]);
            *(float2*)&zs[(r0 + 8) * ZPITCH + col] = make_float2(acc[mt][nt][2], acc[mt][nt][3]);
        }
    }
    __syncthreads();

    // cell epilogue: 64 rows x 32 units
#pragma unroll
    for (int i = 0; i < 8; i++) {
        const int idx = i * 256 + tid;
        const int r = idx >> 5;
        const int u = idx & 31;
        const int b = m0 + r;
        const int hx = (n0 >> 2) + u;

        float4 z4 = *(float4*)&zs[r * ZPITCH + 4 * u];
        uint2 xw2 = *(const uint2*)(g_xw16 + ((size_t)b * TT + t) * FOURH + n0 + 4 * u);
        __half2 xlo = *(__half2*)&xw2.x;
        __half2 xhi = *(__half2*)&xw2.y;

        const float zi = z4.x + __half2float(xlo.x);
        const float zj = z4.y + __half2float(xlo.y);
        const float zf = z4.z + __half2float(xhi.x);
        const float zo = z4.w + __half2float(xhi.y);

        const size_t si = (size_t)b * HH + hx;
        const float c = g_c[si];
        const float hprev = g_h[si];
        const bool m = t < g_seqp[b];

        const float nc = c * sigf(zf + 1.0f) + sigf(zi) * tanhf(zj);
        const float nh = tanhf(nc) * sigf(zo);

        const float co = m ? nc : c;
        const float ho = m ? nh : hprev;
        const float fe = m ? nh : 0.0f;

        g_c[si] = co;
        g_h[si] = ho;
        h_wr[si] = __float2half(ho);
        g_f16[((size_t)b * TT + t) * HH + hx] = __float2half(fe);
    }
}

// ---------------------------------------------------------------------------
// Prep kernels
// ---------------------------------------------------------------------------
__global__ void sort_batches(const int* __restrict__ seq)
{
    __shared__ int hist[130];
    __shared__ int off[130];
    const int tid = threadIdx.x;
    if (tid < 130) hist[tid] = 0;
    __syncthreads();
    for (int b = tid; b < BB; b += 256) atomicAdd(&hist[seq[b]], 1);
    __syncthreads();
    if (tid == 0) {
        int acc = 0;
        for (int v = 128; v >= 1; v--) { off[v] = acc; acc += hist[v]; }
    }
    __syncthreads();
    if (tid < TT) g_nact[tid] = (tid == 0) ? BB : off[tid];   // #seq > t
    __syncthreads();
    if (tid == 0) {
        for (int b = 0; b < BB; b++) {
            const int v = seq[b];
            const int p = off[v]++;
            g_perm[p] = b;
            g_seqp[p] = v;
        }
        int acc = 0;
        for (int b = 0; b < BB; b++) { g_rowoff[b] = acc; acc += g_seqp[b]; }
        g_total[0] = acc;
    }
}

__global__ void fill_rows()
{
    const int bp = blockIdx.x;
    const int s = g_seqp[bp];
    const int off = g_rowoff[bp];
    const int dst0 = bp * TT;
    const int src0 = g_perm[bp] * TT;
    for (int t = threadIdx.x; t < s; t += 128) {
        g_rows[off + t] = dst0 + t;
        g_rowsrc[off + t] = src0 + t;
    }
    if (bp == 0 && threadIdx.x < 128) {      // pad tail tile with safe row 0
        const int total = g_total[0];
        g_rows[total + threadIdx.x] = 0;
        g_rowsrc[total + threadIdx.x] = 0;
    }
}

__global__ void init_state(const float* __restrict__ c_in, const float* __restrict__ h_in)
{
    int i = blockIdx.x * blockDim.x + threadIdx.x;
    if (i < BB * HH) {
        const int bp = i / HH;
        const int hx = i - bp * HH;
        const size_t src = (size_t)g_perm[bp] * HH + hx;
        g_c[i] = c_in[src];
        float h = h_in[src];
        g_h[i] = h;
        g_h16[0][i] = __float2half(h);
    }
}

// Convert only ACTIVE rows of X (one packed row per block of 128 threads).
__global__ __launch_bounds__(128) void convert_x_packed(const float* __restrict__ x)
{
    const int p = blockIdx.x;
    if (p >= g_total[0]) return;
    const size_t row = (size_t)g_rowsrc[p] * FF;
    const int t4 = threadIdx.x * 8;          // 8 elems per thread
    float4 v0 = *(const float4*)(x + row + t4);
    float4 v1 = *(const float4*)(x + row + t4 + 4);
    union { h16 h[8]; uint4 u; } H;
    H.h[0] = __float2half(v0.x); H.h[1] = __float2half(v0.y);
    H.h[2] = __float2half(v0.z); H.h[3] = __float2half(v0.w);
    H.h[4] = __float2half(v1.x); H.h[5] = __float2half(v1.y);
    H.h[6] = __float2half(v1.z); H.h[7] = __float2half(v1.w);
    *(uint4*)(g_x16 + row + t4) = H.u;
}

__global__ void transpose_split(const float* __restrict__ in, h16* __restrict__ oh,
                                h16* __restrict__ ol, int K, int N, int interleave)
{
    __shared__ float tile[32][33];
    const int kb = blockIdx.y * 32;
    const int nb = blockIdx.x * 32;
    const int tx = threadIdx.x;
    for (int r = threadIdx.y; r < 32; r += 8)
        tile[r][tx] = in[(size_t)(kb + r) * N + nb + tx];
    __syncthreads();
    for (int rr = threadIdx.y; rr < 32; rr += 8) {
        float v = tile[tx][rr];
        h16 hi, lo;
        splitw(v, hi, lo);
        int c = nb + rr;
        int n_new = interleave ? ((c & 1023) * 4 + (c >> 10)) : c;
        const size_t o = (size_t)n_new * K + kb + tx;
        oh[o] = hi;
        if (ol) ol[o] = lo;
    }
}

__global__ void permute_bias(const float* __restrict__ b)
{
    int c = blockIdx.x * 256 + threadIdx.x;
    if (c < FOURH) g_bias[(c & 1023) * 4 + (c >> 10)] = b[c];
}

// ---------------------------------------------------------------------------
// kernel_launch
// ---------------------------------------------------------------------------
extern "C" void kernel_launch(void* const* d_in, const int* in_sizes, int n_in,
                              void* d_out, int out_size)
{
    const float* X    = (const float*)d_in[0];
    const int*   seq  = (const int*)d_in[1];
    const float* c_in = (const float*)d_in[2];
    const float* h_in = (const float*)d_in[3];
    const float* W    = (const float*)d_in[4];
    const float* bias = (const float*)d_in[5];
    const float* Wout = (const float*)d_in[6];
    const float* bout = (const float*)d_in[7];
    float* out = (float*)d_out;

    h16 *p_wxh, *p_whh, *p_woh;
    cudaGetSymbolAddress((void**)&p_wxh, g_wx_hi);
    cudaGetSymbolAddress((void**)&p_whh, g_wh_hi);
    cudaGetSymbolAddress((void**)&p_woh, g_wo_hi);

    cudaFuncSetAttribute(gemm_xw_packed, cudaFuncAttributeMaxDynamicSharedMemorySize, SMEM_X);
    cudaFuncSetAttribute(gemm_head_packed, cudaFuncAttributeMaxDynamicSharedMemorySize, SMEM_H);
    cudaFuncSetAttribute(lstm_step_fused, cudaFuncAttributeMaxDynamicSharedMemorySize, SMEM_REC);

    // prep
    sort_batches<<<1, 256>>>(seq);
    fill_rows<<<BB, 128>>>();
    init_state<<<(BB * HH + 255) / 256, 256>>>(c_in, h_in);
    convert_x_packed<<<BT, 128>>>(X);
    transpose_split<<<dim3(FOURH / 32, FF / 32), dim3(32, 8)>>>(W, p_wxh, nullptr, FF, FOURH, 1);
    transpose_split<<<dim3(FOURH / 32, HH / 32), dim3(32, 8)>>>(W + (size_t)FF * FOURH, p_whh, nullptr, HH, FOURH, 1);
    transpose_split<<<dim3(NOUT / 32, HH / 32), dim3(32, 8)>>>(Wout, p_woh, nullptr, HH, NOUT, 0);
    permute_bias<<<FOURH / 256, 256>>>(bias);

    // XW over packed active rows (BM=128, fp16 out)
    gemm_xw_packed<<<dim3(FOURH / 128, BT / 128), 256, SMEM_X>>>();

    // recurrence: per-step launches, BM=64/BN=128 tiles, single-term Wh, 4 stages
    for (int t = 0; t < TT; t++)
        lstm_step_fused<<<dim3(FOURH / 128, BB / 64), 256, SMEM_REC>>>(t);

    // head over packed active rows + bias fill for inactive rows
    head_bias_fill<<<BB, 256>>>(bout, out);
    gemm_head_packed<<<dim3(NOUT / 128, BT / 64), 256, SMEM_H>>>(bout, out);
}

// round 17
// speedup vs baseline: 1.4109x; 1.0008x over previous
#include <cuda_runtime.h>
#include <cuda_fp16.h>
#include <math.h>
#include <stdint.h>

#define BB 512
#define TT 128
#define FF 1024
#define HH 1024
#define NOUT 256
#define FOURH 4096
#define BT 65536
#define NCH 8                    // xw timestep chunks (16 steps each)

typedef __half h16;

// ---------------------------------------------------------------------------
// Device-global scratch (sorted-batch order unless noted)
// ---------------------------------------------------------------------------
__device__ h16   g_xw16[(size_t)BT * FOURH];   // X @ Wx + b, gate-interleaved cols (fp16)
__device__ float g_c[BB * HH];
__device__ float g_bias[FOURH];                // permuted bias
__device__ h16   g_x16[(size_t)BT * FF];       // X as fp16 (ORIGINAL batch order; active rows only)
__device__ h16   g_f16[(size_t)BT * HH];       // masked h outputs (zero-init; inactive rows never written)
__device__ h16   g_h16[2][BB * HH];            // double-buffered h state, fp16
__device__ h16   g_wx_hi[(size_t)FOURH * FF];  // Wx^T [4H,F] K-major, interleaved rows
__device__ h16   g_wh_hi[(size_t)FOURH * HH];  // Wh^T (single fp16 term)
__device__ h16   g_wo_hi[NOUT * HH];
__device__ int   g_perm[BB];                   // sorted idx -> original idx
__device__ int   g_seqp[BB];                   // seq_len in sorted order (descending)
__device__ int   g_nact[TT];                   // #batches with seq_len > t
__device__ int   g_total[1];                   // total active rows
__device__ int   g_chunkoff[NCH];              // packed-row offset per t-chunk
__device__ int   g_chunkcnt[NCH];              // packed-row count per t-chunk
__device__ int   g_bpchunk[NCH * BB];          // per (chunk, bp) start offset
__device__ int   g_rows[BT + 128];             // packed i -> sorted flat row (bp*TT+t), chunk-major
__device__ int   g_rowsrc[BT + 128];           // packed i -> original flat row (perm[bp]*TT+t)

// ---------------------------------------------------------------------------
// Baseline-PTX helpers (legal on plain sm_103 target)
// ---------------------------------------------------------------------------
__device__ __forceinline__ uint32_t smem_u32(const void* p) {
    uint32_t a;
    asm("{ .reg .u64 t; cvta.to.shared.u64 t, %1; cvt.u32.u64 %0, t; }"
        : "=r"(a) : "l"(p));
    return a;
}
__device__ __forceinline__ void cp16(uint32_t dst, const void* src) {
    asm volatile("cp.async.cg.shared.global [%0], [%1], 16;"
                 :: "r"(dst), "l"(src) : "memory");
}
__device__ __forceinline__ void ldsm4(uint32_t* r, uint32_t addr) {
    asm volatile("ldmatrix.sync.aligned.m8n8.x4.shared.b16 {%0,%1,%2,%3}, [%4];"
                 : "=r"(r[0]), "=r"(r[1]), "=r"(r[2]), "=r"(r[3]) : "r"(addr));
}
__device__ __forceinline__ void mma16816(float* d, const uint32_t* a, const uint32_t* b) {
    asm volatile(
        "mma.sync.aligned.m16n8k16.row.col.f32.f16.f16.f32 "
        "{%0,%1,%2,%3}, {%4,%5,%6,%7}, {%8,%9}, {%0,%1,%2,%3};"
        : "+f"(d[0]), "+f"(d[1]), "+f"(d[2]), "+f"(d[3])
        : "r"(a[0]), "r"(a[1]), "r"(a[2]), "r"(a[3]), "r"(b[0]), "r"(b[1]));
}

// ---------------------------------------------------------------------------
// GEMM tile machinery. BM=MT*32 rows, BN=NT*32 cols, BK=32, 256 threads.
// ---------------------------------------------------------------------------
#define ROWB 80

template <int MT, int NT, int NB, bool PACKED>
__device__ __forceinline__ void load_stage(
    uint32_t stg, const h16* __restrict__ A, const int* __restrict__ aidx,
    const h16* __restrict__ Bh, const h16* __restrict__ Bl,
    int n0, int k0, int K, int tid)
{
    constexpr int BM = MT * 32;
    constexpr int BN = NT * 32;
    constexpr uint32_t OFFB = (uint32_t)BM * ROWB;
    constexpr uint32_t BTERM = (uint32_t)BN * ROWB;
#pragma unroll
    for (int i = 0; i < BM * 4 / 256; i++) {
        const int c = tid + i * 256;
        const int row = c >> 2;
        const int seg = c & 3;
        const h16* src = PACKED ? A + (size_t)aidx[row] * K + k0 + seg * 8
                                : A + (size_t)row * K + k0 + seg * 8;
        cp16(stg + (uint32_t)(row * ROWB + seg * 16), src);
    }
#pragma unroll
    for (int i = 0; i < BN * 4 / 256; i++) {
        const int c = tid + i * 256;
        const int row = c >> 2;
        const int seg = c & 3;
        const uint32_t soff = (uint32_t)(row * ROWB + seg * 16);
        const size_t gb = (size_t)(n0 + row) * K + k0 + seg * 8;
        cp16(stg + OFFB + soff, Bh + gb);
        if (NB == 2) cp16(stg + OFFB + BTERM + soff, Bl + gb);
    }
}

template <int MT, int NT, int NB, int NST, bool PACKED>
__device__ __forceinline__ void gemm_mainloop(
    uint32_t SM, const h16* __restrict__ A, const int* __restrict__ aidx,
    const h16* __restrict__ Bh, const h16* __restrict__ Bl,
    int n0, int K, int tid, float acc[MT][NT][4])
{
    constexpr int BM = MT * 32;
    constexpr int BN = NT * 32;
    constexpr uint32_t OFFB = (uint32_t)BM * ROWB;
    constexpr uint32_t BTERM = (uint32_t)BN * ROWB;
    constexpr uint32_t STG_B = OFFB + NB * BTERM;
    const int lane = tid & 31;
    const int wid  = tid >> 5;
    const int wm   = wid & 1;
    const int wn   = wid >> 1;
    const int NC = K >> 5;

#pragma unroll
    for (int s = 0; s < NST - 1; s++) {
        load_stage<MT, NT, NB, PACKED>(SM + s * STG_B, A, aidx, Bh, Bl, n0, s * 32, K, tid);
        asm volatile("cp.async.commit_group;" ::: "memory");
    }

    const int arow = wm * (MT * 16) + (lane & 15);
    const uint32_t akoff = (uint32_t)((lane >> 4) * 16);
    const int bsel = lane >> 3;
    const int bn = wn * (NT * 8) + ((bsel >> 1) << 3) + (lane & 7);
    const uint32_t bkoff = (uint32_t)((bsel & 1) * 16);

    for (int it = 0; it < NC; it++) {
        asm volatile("cp.async.wait_group %0;" :: "n"(NST - 2) : "memory");
        __syncthreads();

        const int nx = it + NST - 1;
        if (nx < NC)
            load_stage<MT, NT, NB, PACKED>(SM + (uint32_t)(nx % NST) * STG_B,
                                           A, aidx, Bh, Bl, n0, nx * 32, K, tid);
        asm volatile("cp.async.commit_group;" ::: "memory");

        const uint32_t stg = SM + (uint32_t)(it % NST) * STG_B;
#pragma unroll
        for (int ks = 0; ks < 2; ks++) {
            uint32_t ah[MT][4], bh[NT][2], bl[NT][2];
            const uint32_t ak = (uint32_t)(ks * 32) + akoff;
#pragma unroll
            for (int mt = 0; mt < MT; mt++)
                ldsm4(ah[mt], stg + (uint32_t)((arow + mt * 16) * ROWB) + ak);
            const uint32_t bk = (uint32_t)(ks * 32) + bkoff;
#pragma unroll
            for (int np = 0; np < NT / 2; np++) {
                const uint32_t bd = stg + OFFB + (uint32_t)((bn + np * 16) * ROWB) + bk;
                uint32_t tr[4];
                ldsm4(tr, bd);
                bh[2 * np][0] = tr[0]; bh[2 * np][1] = tr[1];
                bh[2 * np + 1][0] = tr[2]; bh[2 * np + 1][1] = tr[3];
                if (NB == 2) {
                    ldsm4(tr, bd + BTERM);
                    bl[2 * np][0] = tr[0]; bl[2 * np][1] = tr[1];
                    bl[2 * np + 1][0] = tr[2]; bl[2 * np + 1][1] = tr[3];
                }
            }
#pragma unroll
            for (int mt = 0; mt < MT; mt++)
#pragma unroll
                for (int nt = 0; nt < NT; nt++) {
                    mma16816(acc[mt][nt], ah[mt], bh[nt]);
                    if (NB == 2) mma16816(acc[mt][nt], ah[mt], bl[nt]);
                }
        }
    }
}

// Scatter epilogue (fp32 out).
template <int MT, int NT>
__device__ __forceinline__ void store_scatter(
    float acc[MT][NT][4], float* __restrict__ Cbase, const int* __restrict__ rows,
    const float* __restrict__ bias, int N, int n0, int tid, int nvalid)
{
    const int lane = tid & 31;
    const int wid  = tid >> 5;
    const int wm   = wid & 1;
    const int wn   = wid >> 1;
    const int colq = (lane & 3) * 2;
    const int rowq = lane >> 2;
    float bx[NT], by[NT];
#pragma unroll
    for (int nt = 0; nt < NT; nt++) {
        const int col = wn * (NT * 8) + nt * 8 + colq;
        float2 bv = *(const float2*)(bias + n0 + col);
        bx[nt] = bv.x; by[nt] = bv.y;
    }
#pragma unroll
    for (int mt = 0; mt < MT; mt++) {
        const int r0 = wm * (MT * 16) + mt * 16 + rowq;
#pragma unroll
        for (int half = 0; half < 2; half++) {
            const int rloc = r0 + half * 8;
            if (rloc < nvalid) {
                float* C = Cbase + (size_t)rows[rloc] * N;
#pragma unroll
                for (int nt = 0; nt < NT; nt++) {
                    const int col = wn * (NT * 8) + nt * 8 + colq;
                    *(float2*)(C + n0 + col) =
                        make_float2(acc[mt][nt][2 * half] + bx[nt],
                                    acc[mt][nt][2 * half + 1] + by[nt]);
                }
            }
        }
    }
}

// Scatter epilogue (fp16 out) for g_xw16.
template <int MT, int NT>
__device__ __forceinline__ void store_scatter_h16(
    float acc[MT][NT][4], h16* __restrict__ Cbase, const int* __restrict__ rows,
    const float* __restrict__ bias, int N, int n0, int tid, int nvalid)
{
    const int lane = tid & 31;
    const int wid  = tid >> 5;
    const int wm   = wid & 1;
    const int wn   = wid >> 1;
    const int colq = (lane & 3) * 2;
    const int rowq = lane >> 2;
    float bx[NT], by[NT];
#pragma unroll
    for (int nt = 0; nt < NT; nt++) {
        const int col = wn * (NT * 8) + nt * 8 + colq;
        float2 bv = *(const float2*)(bias + n0 + col);
        bx[nt] = bv.x; by[nt] = bv.y;
    }
#pragma unroll
    for (int mt = 0; mt < MT; mt++) {
        const int r0 = wm * (MT * 16) + mt * 16 + rowq;
#pragma unroll
        for (int half = 0; half < 2; half++) {
            const int rloc = r0 + half * 8;
            if (rloc < nvalid) {
                h16* C = Cbase + (size_t)rows[rloc] * N;
#pragma unroll
                for (int nt = 0; nt < NT; nt++) {
                    const int col = wn * (NT * 8) + nt * 8 + colq;
                    __half2 hv = __floats2half2_rn(acc[mt][nt][2 * half] + bx[nt],
                                                   acc[mt][nt][2 * half + 1] + by[nt]);
                    *(__half2*)(C + n0 + col) = hv;
                }
            }
        }
    }
}

// ---------------------------------------------------------------------------
// Chunked packed XW GEMM: BM=128 (MT=4), rows from chunk-major packed list.
// ---------------------------------------------------------------------------
#define SMEM_X (4 * (128 * ROWB + 128 * ROWB))   // 81920
__global__ __launch_bounds__(256, 2)
void gemm_xw_packed(int chunk)
{
    const int cnt = g_chunkcnt[chunk];
    const int ts = blockIdx.y * 128;
    if (ts >= cnt) return;
    const int base = g_chunkoff[chunk] + ts;
    extern __shared__ char smem_raw[];
    const uint32_t SM = smem_u32(smem_raw);
    const int tid = threadIdx.x;
    const int n0 = blockIdx.x * 128;

    float acc[4][4][4];
#pragma unroll
    for (int a = 0; a < 4; a++)
#pragma unroll
        for (int b = 0; b < 4; b++)
#pragma unroll
            for (int cc = 0; cc < 4; cc++) acc[a][b][cc] = 0.0f;

    gemm_mainloop<4, 4, 1, 4, true>(SM, g_x16, g_rowsrc + base, g_wx_hi, nullptr,
                                    n0, FF, tid, acc);
    store_scatter_h16<4, 4>(acc, g_xw16, g_rows + base, g_bias, FOURH, n0, tid, cnt - ts);
}

// ---------------------------------------------------------------------------
// Packed head GEMM: BM=64 tiles (MT=2).
// ---------------------------------------------------------------------------
#define SMEM_H (4 * (64 * ROWB + 128 * ROWB))    // 61440
__global__ __launch_bounds__(256, 2)
void gemm_head_packed(const float* __restrict__ bout, float* __restrict__ out)
{
    const int ts = blockIdx.y * 64;
    const int total = g_total[0];
    if (ts >= total) return;
    extern __shared__ char smem_raw[];
    const uint32_t SM = smem_u32(smem_raw);
    const int tid = threadIdx.x;
    const int n0 = blockIdx.x * 128;

    float acc[2][4][4];
#pragma unroll
    for (int a = 0; a < 2; a++)
#pragma unroll
        for (int b = 0; b < 4; b++)
#pragma unroll
            for (int cc = 0; cc < 4; cc++) acc[a][b][cc] = 0.0f;

    gemm_mainloop<2, 4, 1, 4, true>(SM, g_f16, g_rows + ts, g_wo_hi, nullptr,
                                    n0, HH, tid, acc);
    store_scatter<2, 4>(acc, out, g_rowsrc + ts, bout, NOUT, n0, tid, total - ts);
}

// Bias fill for inactive head rows (logits = bias there).
__global__ void head_bias_fill(const float* __restrict__ bout, float* __restrict__ out)
{
    const int bp = blockIdx.x;
    const int s = g_seqp[bp];
    const int nrows = TT - s;
    if (nrows <= 0) return;
    const size_t base = ((size_t)g_perm[bp] * TT + s) * NOUT;
    for (int i = threadIdx.x; i < nrows * 64; i += 256) {
        const int r = i >> 6;
        const int c = (i & 63) * 4;
        *(float4*)(out + base + (size_t)r * NOUT + c) = *(const float4*)(bout + c);
    }
}

// ---------------------------------------------------------------------------
// Fused recurrent step: BM=64, BN=128 (NT=4), single-term Wh, 4 stages.
// ---------------------------------------------------------------------------
#define SMEM_REC (4 * (64 * ROWB + 128 * ROWB))   // 61440
__device__ __forceinline__ float sigf(float x) { return 1.0f / (1.0f + expf(-x)); }
__device__ __forceinline__ void splitw(float v, h16& hi, h16& lo) {
    hi = __float2half(v);
    lo = __float2half(v - __half2float(hi));
}

#define ZPITCH 132

__global__ __launch_bounds__(256, 2)
void lstm_step_fused(int t)
{
    const int m0 = blockIdx.y * 64;
    if (m0 >= g_nact[t]) return;

    extern __shared__ char smem_raw[];
    const uint32_t SM = smem_u32(smem_raw);
    float* zs = (float*)smem_raw;
    const int tid  = threadIdx.x;
    const int lane = tid & 31;
    const int wid  = tid >> 5;
    const int wm   = wid & 1;
    const int wn   = wid >> 1;
    const int n0 = blockIdx.x * 128;

    const h16* __restrict__ h_rd = g_h16[t & 1] + (size_t)m0 * HH;
    h16* __restrict__ h_wr = g_h16[(t + 1) & 1];

    float acc[2][4][4];
#pragma unroll
    for (int a = 0; a < 2; a++)
#pragma unroll
        for (int b = 0; b < 4; b++)
#pragma unroll
            for (int cc = 0; cc < 4; cc++) acc[a][b][cc] = 0.0f;

    gemm_mainloop<2, 4, 1, 4, false>(SM, h_rd, nullptr, g_wh_hi, nullptr,
                                     n0, HH, tid, acc);

    __syncthreads();

    // acc -> smem z tile (64 x 128)
    const int colq = (lane & 3) * 2;
    const int rowq = lane >> 2;
#pragma unroll
    for (int nt = 0; nt < 4; nt++) {
        const int col = wn * 32 + nt * 8 + colq;
#pragma unroll
        for (int mt = 0; mt < 2; mt++) {
            const int r0 = wm * 32 + mt * 16 + rowq;
            *(float2*)&zs[r0 * ZPITCH + col] = make_float2(acc[mt][nt][0], acc[mt][nt][1]);
            *(float2*)&zs[(r0 + 8) * ZPITCH + col] = make_float2(acc[mt][nt][2], acc[mt][nt][3]);
        }
    }
    __syncthreads();

    // cell epilogue: 64 rows x 32 units
#pragma unroll
    for (int i = 0; i < 8; i++) {
        const int idx = i * 256 + tid;
        const int r = idx >> 5;
        const int u = idx & 31;
        const int b = m0 + r;
        const int hx = (n0 >> 2) + u;

        float4 z4 = *(float4*)&zs[r * ZPITCH + 4 * u];
        uint2 xw2 = *(const uint2*)(g_xw16 + ((size_t)b * TT + t) * FOURH + n0 + 4 * u);
        __half2 xlo = *(__half2*)&xw2.x;
        __half2 xhi = *(__half2*)&xw2.y;

        const float zi = z4.x + __half2float(xlo.x);
        const float zj = z4.y + __half2float(xlo.y);
        const float zf = z4.z + __half2float(xhi.x);
        const float zo = z4.w + __half2float(xhi.y);

        const size_t si = (size_t)b * HH + hx;
        const float c = g_c[si];
        const h16 hprev16 = h_rd[(size_t)r * HH + hx];
        const bool m = t < g_seqp[b];

        const float nc = c * sigf(zf + 1.0f) + sigf(zi) * tanhf(zj);
        const float nh = tanhf(nc) * sigf(zo);

        g_c[si] = m ? nc : c;
        const h16 nh16 = __float2half(nh);
        h_wr[si] = m ? nh16 : hprev16;
        g_f16[((size_t)b * TT + t) * HH + hx] = m ? nh16 : __float2half(0.0f);
    }
}

// ---------------------------------------------------------------------------
// Prep kernels
// ---------------------------------------------------------------------------
__global__ void sort_batches(const int* __restrict__ seq)
{
    __shared__ int hist[130];
    __shared__ int off[130];
    const int tid = threadIdx.x;
    if (tid < 130) hist[tid] = 0;
    __syncthreads();
    for (int b = tid; b < BB; b += 256) atomicAdd(&hist[seq[b]], 1);
    __syncthreads();
    if (tid == 0) {
        int acc = 0;
        for (int v = 128; v >= 1; v--) { off[v] = acc; acc += hist[v]; }
    }
    __syncthreads();
    if (tid < TT) g_nact[tid] = (tid == 0) ? BB : off[tid];   // #seq > t
    __syncthreads();
    if (tid == 0) {
        for (int b = 0; b < BB; b++) {
            const int v = seq[b];
            const int p = off[v]++;
            g_perm[p] = b;
            g_seqp[p] = v;
        }
        // chunk-major packed layout offsets
        int acc = 0;
        for (int c = 0; c < NCH; c++) {
            g_chunkoff[c] = acc;
            for (int bp = 0; bp < BB; bp++) {
                g_bpchunk[c * BB + bp] = acc;
                int v = g_seqp[bp] - 16 * c;
                v = v < 0 ? 0 : (v > 16 ? 16 : v);
                acc += v;
            }
            g_chunkcnt[c] = acc - g_chunkoff[c];
        }
        g_total[0] = acc;
    }
}

__global__ void fill_rows()
{
    const int bp = blockIdx.x;
    const int s = g_seqp[bp];
    const int dst0 = bp * TT;
    const int src0 = g_perm[bp] * TT;
    for (int t = threadIdx.x; t < s; t += 128) {
        const int c = t >> 4;
        const int pos = g_bpchunk[c * BB + bp] + (t & 15);
        g_rows[pos] = dst0 + t;
        g_rowsrc[pos] = src0 + t;
    }
    if (bp == 0 && threadIdx.x < 128) {      // pad tail tile with safe row 0
        const int total = g_total[0];
        g_rows[total + threadIdx.x] = 0;
        g_rowsrc[total + threadIdx.x] = 0;
    }
}

__global__ void init_state(const float* __restrict__ c_in, const float* __restrict__ h_in)
{
    int i = blockIdx.x * blockDim.x + threadIdx.x;
    if (i < BB * HH) {
        const int bp = i / HH;
        const int hx = i - bp * HH;
        const size_t src = (size_t)g_perm[bp] * HH + hx;
        g_c[i] = c_in[src];
        g_h16[0][i] = __float2half(h_in[src]);
    }
}

// Convert only ACTIVE rows of X (one packed row per block of 128 threads).
__global__ __launch_bounds__(128) void convert_x_packed(const float* __restrict__ x)
{
    const int p = blockIdx.x;
    if (p >= g_total[0]) return;
    const size_t row = (size_t)g_rowsrc[p] * FF;
    const int t4 = threadIdx.x * 8;
    float4 v0 = *(const float4*)(x + row + t4);
    float4 v1 = *(const float4*)(x + row + t4 + 4);
    union { h16 h[8]; uint4 u; } H;
    H.h[0] = __float2half(v0.x); H.h[1] = __float2half(v0.y);
    H.h[2] = __float2half(v0.z); H.h[3] = __float2half(v0.w);
    H.h[4] = __float2half(v1.x); H.h[5] = __float2half(v1.y);
    H.h[6] = __float2half(v1.z); H.h[7] = __float2half(v1.w);
    *(uint4*)(g_x16 + row + t4) = H.u;
}

__global__ void transpose_split(const float* __restrict__ in, h16* __restrict__ oh,
                                h16* __restrict__ ol, int K, int N, int interleave)
{
    __shared__ float tile[32][33];
    const int kb = blockIdx.y * 32;
    const int nb = blockIdx.x * 32;
    const int tx = threadIdx.x;
    for (int r = threadIdx.y; r < 32; r += 8)
        tile[r][tx] = in[(size_t)(kb + r) * N + nb + tx];
    __syncthreads();
    for (int rr = threadIdx.y; rr < 32; rr += 8) {
        float v = tile[tx][rr];
        h16 hi, lo;
        splitw(v, hi, lo);
        int c = nb + rr;
        int n_new = interleave ? ((c & 1023) * 4 + (c >> 10)) : c;
        const size_t o = (size_t)n_new * K + kb + tx;
        oh[o] = hi;
        if (ol) ol[o] = lo;
    }
}

__global__ void permute_bias(const float* __restrict__ b)
{
    int c = blockIdx.x * 256 + threadIdx.x;
    if (c < FOURH) g_bias[(c & 1023) * 4 + (c >> 10)] = b[c];
}

// ---------------------------------------------------------------------------
// kernel_launch: forks a second stream during capture to overlap XW chunks
// 1..7 with the recurrence; step 16c gated on event ev[c].
// ---------------------------------------------------------------------------
extern "C" void kernel_launch(void* const* d_in, const int* in_sizes, int n_in,
                              void* d_out, int out_size)
{
    const float* X    = (const float*)d_in[0];
    const int*   seq  = (const int*)d_in[1];
    const float* c_in = (const float*)d_in[2];
    const float* h_in = (const float*)d_in[3];
    const float* W    = (const float*)d_in[4];
    const float* bias = (const float*)d_in[5];
    const float* Wout = (const float*)d_in[6];
    const float* bout = (const float*)d_in[7];
    float* out = (float*)d_out;

    h16 *p_wxh, *p_whh, *p_woh;
    cudaGetSymbolAddress((void**)&p_wxh, g_wx_hi);
    cudaGetSymbolAddress((void**)&p_whh, g_wh_hi);
    cudaGetSymbolAddress((void**)&p_woh, g_wo_hi);

    cudaFuncSetAttribute(gemm_xw_packed, cudaFuncAttributeMaxDynamicSharedMemorySize, SMEM_X);
    cudaFuncSetAttribute(gemm_head_packed, cudaFuncAttributeMaxDynamicSharedMemorySize, SMEM_H);
    cudaFuncSetAttribute(lstm_step_fused, cudaFuncAttributeMaxDynamicSharedMemorySize, SMEM_REC);

    cudaStream_t s2;
    cudaStreamCreateWithFlags(&s2, cudaStreamNonBlocking);
    cudaEvent_t evA, evc[NCH];
    cudaEventCreateWithFlags(&evA, cudaEventDisableTiming);
    for (int c = 1; c < NCH; c++)
        cudaEventCreateWithFlags(&evc[c], cudaEventDisableTiming);

    // prep (default stream)
    sort_batches<<<1, 256>>>(seq);
    fill_rows<<<BB, 128>>>();
    init_state<<<(BB * HH + 255) / 256, 256>>>(c_in, h_in);
    convert_x_packed<<<BT, 128>>>(X);
    transpose_split<<<dim3(FOURH / 32, FF / 32), dim3(32, 8)>>>(W, p_wxh, nullptr, FF, FOURH, 1);
    transpose_split<<<dim3(FOURH / 32, HH / 32), dim3(32, 8)>>>(W + (size_t)FF * FOURH, p_whh, nullptr, HH, FOURH, 1);
    transpose_split<<<dim3(NOUT / 32, HH / 32), dim3(32, 8)>>>(Wout, p_woh, nullptr, HH, NOUT, 0);
    permute_bias<<<FOURH / 256, 256>>>(bias);

    // XW chunk 0 on main stream (needed before step 0)
    gemm_xw_packed<<<dim3(FOURH / 128, 64), 256, SMEM_X>>>(0);
    cudaEventRecord(evA, 0);

    // XW chunks 1..7 on the side stream
    cudaStreamWaitEvent(s2, evA, 0);
    for (int c = 1; c < NCH; c++) {
        gemm_xw_packed<<<dim3(FOURH / 128, 64), 256, SMEM_X, s2>>>(c);
        cudaEventRecord(evc[c], s2);
    }

    // recurrence, gated per 16-step chunk
    for (int t = 0; t < TT; t++) {
        if (t > 0 && (t & 15) == 0)
            cudaStreamWaitEvent(0, evc[t >> 4], 0);
        lstm_step_fused<<<dim3(FOURH / 128, BB / 64), 256, SMEM_REC>>>(t);
    }

    // head
    head_bias_fill<<<BB, 256>>>(bout, out);
    gemm_head_packed<<<dim3(NOUT / 128, BT / 64), 256, SMEM_H>>>(bout, out);
}